// round 16
// baseline (speedup 1.0000x reference)
#include <cuda_runtime.h>
#include <cuda_bf16.h>
#include <cstdint>

// Problem constants
#define B_  4
#define S_  2048
#define D_  1024
#define H_  16
#define HD_ 64
#define M_  (B_ * S_)   // 8192 rows

// Scratch (allocation-free rule: __device__ globals)
__device__ __nv_bfloat16 g_q[M_ * D_];              // bf16 Q [tok][D]
__device__ __nv_bfloat16 g_k[M_ * D_];              // bf16 K [tok][D]
__device__ __nv_bfloat16 g_vt[B_ * H_ * 64 * S_];   // V^T hi [(b,h,d)][s]
__device__ __nv_bfloat16 g_vlt[B_ * H_ * 64 * S_];  // V^T lo
__device__ float g_cs[B_ * H_ * 32 * 64];           // prefix tile colsums of V
__device__ __nv_bfloat16 g_xh[M_ * D_], g_xl[M_ * D_];    // x hi/lo
__device__ __nv_bfloat16 g_ch[M_ * D_], g_cl[M_ * D_];    // ctx hi/lo
__device__ __nv_bfloat16 g_wh[4 * D_ * D_];               // W^T hi [N][K] x4
__device__ __nv_bfloat16 g_wl[4 * D_ * D_];               // W^T lo

// ---------------------------------------------------------------------------
// cp.async / ldmatrix helpers
// ---------------------------------------------------------------------------
__device__ __forceinline__ void cp_async16(void* smem, const void* gmem) {
    uint32_t s = (uint32_t)__cvta_generic_to_shared(smem);
    asm volatile("cp.async.cg.shared.global [%0], [%1], 16;\n" :: "r"(s), "l"(gmem));
}
__device__ __forceinline__ void cp_commit() {
    asm volatile("cp.async.commit_group;\n");
}
template <int N>
__device__ __forceinline__ void cp_wait() {
    asm volatile("cp.async.wait_group %0;\n" :: "n"(N));
}

#define LDSM_X4(r0, r1, r2, r3, a)                                            \
    asm volatile("ldmatrix.sync.aligned.m8n8.x4.shared.b16 {%0,%1,%2,%3}, [%4];" \
                 : "=r"(r0), "=r"(r1), "=r"(r2), "=r"(r3) : "r"(a))

#define MMA_BF16(c, a, b)                                                     \
    asm volatile(                                                             \
        "mma.sync.aligned.m16n8k16.row.col.f32.bf16.bf16.f32 "                \
        "{%0,%1,%2,%3},{%4,%5,%6,%7},{%8,%9},{%0,%1,%2,%3};"                  \
        : "+f"(c[0]), "+f"(c[1]), "+f"(c[2]), "+f"(c[3])                      \
        : "r"(a[0]), "r"(a[1]), "r"(a[2]), "r"(a[3]), "r"(b[0]), "r"(b[1]))

__device__ __forceinline__ void split_bf16(float x, __nv_bfloat16& h, __nv_bfloat16& l) {
    h = __float2bfloat16_rn(x);
    l = __float2bfloat16_rn(x - __bfloat162float(h));
}

// ---------------------------------------------------------------------------
// Prep: elementwise fp32 -> bf16 hi/lo split (x).
// ---------------------------------------------------------------------------
__global__ __launch_bounds__(256) void fsplit(const float* __restrict__ src,
                                              __nv_bfloat16* __restrict__ h,
                                              __nv_bfloat16* __restrict__ l) {
    const int i = blockIdx.x * 256 + threadIdx.x;
    float4 v = ((const float4*)src)[i];
    __nv_bfloat16 h0, h1, h2, h3, l0, l1, l2, l3;
    split_bf16(v.x, h0, l0);
    split_bf16(v.y, h1, l1);
    split_bf16(v.z, h2, l2);
    split_bf16(v.w, h3, l3);
    __nv_bfloat162* hp = (__nv_bfloat162*)h;
    __nv_bfloat162* lp = (__nv_bfloat162*)l;
    hp[2 * i]     = __nv_bfloat162{h0, h1};
    hp[2 * i + 1] = __nv_bfloat162{h2, h3};
    lp[2 * i]     = __nv_bfloat162{l0, l1};
    lp[2 * i + 1] = __nv_bfloat162{l2, l3};
}

// ---------------------------------------------------------------------------
// Prep: W [K][N] -> W^T hi/lo bf16 [N][K], 32x32 smem tile transpose.
// ---------------------------------------------------------------------------
__global__ __launch_bounds__(256) void wsplit_t(const float* __restrict__ W0,
                                                const float* __restrict__ W1,
                                                const float* __restrict__ W2,
                                                const float* __restrict__ W3,
                                                __nv_bfloat16* __restrict__ dh,
                                                __nv_bfloat16* __restrict__ dl) {
    __shared__ float t[32][33];
    const float* W = (blockIdx.z == 0) ? W0 : (blockIdx.z == 1) ? W1
                   : (blockIdx.z == 2) ? W2 : W3;
    dh += (size_t)blockIdx.z * D_ * D_;
    dl += (size_t)blockIdx.z * D_ * D_;
    const int kx = blockIdx.x * 32, ny = blockIdx.y * 32;
    const int tx = threadIdx.x & 31, ty = threadIdx.x >> 5;
#pragma unroll
    for (int r = 0; r < 4; r++) {
        const int row = ty + r * 8;
        t[row][tx] = W[(size_t)(kx + row) * D_ + ny + tx];
    }
    __syncthreads();
#pragma unroll
    for (int r = 0; r < 4; r++) {
        const int row = ty + r * 8;
        __nv_bfloat16 h, l;
        split_bf16(t[tx][row], h, l);
        dh[(size_t)(ny + row) * D_ + kx + tx] = h;
        dl[(size_t)(ny + row) * D_ + kx + tx] = l;
    }
}

// ---------------------------------------------------------------------------
// Prep: fused per-tile colsum + prefix over tiles. Warp-per-d-row, lane-
// contiguous bf16x2 reads (coalesced in V^T layout), warp reduce per tile.
// ---------------------------------------------------------------------------
__global__ __launch_bounds__(256) void vcolsum(const __nv_bfloat16* __restrict__ vt,
                                               const __nv_bfloat16* __restrict__ vlt,
                                               float* __restrict__ cs) {
    const int h = blockIdx.x, b = blockIdx.y;
    const int wid = threadIdx.x >> 5, lane = threadIdx.x & 31;
#pragma unroll
    for (int dd = 0; dd < 8; dd++) {
        const int d = wid * 8 + dd;
        const size_t rbase = (((size_t)b * H_ + h) * 64 + d) * S_;
        float run = 0.f;
        for (int t = 0; t < 32; t++) {
            const __nv_bfloat162 a = *(const __nv_bfloat162*)(vt + rbase + t * 64 + lane * 2);
            const __nv_bfloat162 c = *(const __nv_bfloat162*)(vlt + rbase + t * 64 + lane * 2);
            float s = __bfloat162float(a.x) + __bfloat162float(a.y) +
                      __bfloat162float(c.x) + __bfloat162float(c.y);
#pragma unroll
            for (int o = 16; o >= 1; o >>= 1)
                s += __shfl_xor_sync(0xffffffffu, s, o);
            run += s;
            if (lane == 0)
                cs[(((size_t)b * H_ + h) * 32 + t) * 64 + d] = run;
        }
    }
}

// ---------------------------------------------------------------------------
// bf16 tensor-core GEMM, fused over up to 3 weights. Heavy-first mapping:
// blockIdx.x 0-7 -> sel 2 (3-pass V), 8-15 -> sel 0 (Q), 16-23 -> sel 1 (K).
// Fragment loads via ldmatrix.x4 (pitch 80B: conflict-free phases).
// Single-sync pipelined mainloop, 2 CTAs/SM.
// ---------------------------------------------------------------------------
#define GP 40                     // smem pitch in bf16 (80 bytes)
#define PLANE (128 * GP)          // 5120 bf16 per plane
#define STAGE (4 * PLANE)         // Ah, Al, Bh, Bl

__global__ __launch_bounds__(256, 2) void gemm_bf16x3(
    const __nv_bfloat16* __restrict__ Ah, const __nv_bfloat16* __restrict__ Al,
    const __nv_bfloat16* __restrict__ BhBase,
    const __nv_bfloat16* __restrict__ BlBase,
    const float* __restrict__ bias, float* __restrict__ Cf,
    __nv_bfloat16* __restrict__ Qo, __nv_bfloat16* __restrict__ Ko,
    __nv_bfloat16* __restrict__ Vto, __nv_bfloat16* __restrict__ Vlto,
    int qkv_mode) {
    const int K = D_, N = D_;
    extern __shared__ __nv_bfloat16 smb[];
    const uint32_t sb32 = (uint32_t)__cvta_generic_to_shared(smb);

    const int selraw = blockIdx.x >> 3;
    const int sel = qkv_mode ? ((selraw == 0) ? 2 : selraw - 1) : selraw;
    const int bx = blockIdx.x & 7;
    const int by = blockIdx.y;
    const bool full = (qkv_mode == 0) || (sel == 2);
    const __nv_bfloat16* Bh = BhBase + (size_t)sel * D_ * D_;
    const __nv_bfloat16* Bl = BlBase + (size_t)sel * D_ * D_;

    const int tid = threadIdx.x;
    const int wid = tid >> 5, lane = tid & 31;
    const int grp = lane >> 2, tg = lane & 3;
    const int wm = wid & 3;
    const int wn = wid >> 2;
    // ldmatrix lane-address components
    const int lrowA = lane & 15;
    const int lcolA = (lane & 16) ? 16 : 0;
    const int nfselB = (lane >> 4) & 1;
    const int lrowB = lane & 7;
    const int lcolB = (lane & 8) ? 16 : 0;

    float acc[2][8][4] = {};

    const __nv_bfloat16* srcA_h = Ah + (size_t)(by * 128) * K;
    const __nv_bfloat16* srcA_l = Al + (size_t)(by * 128) * K;
    const __nv_bfloat16* srcB_h = Bh + (size_t)(bx * 128) * K;
    const __nv_bfloat16* srcB_l = Bl + (size_t)(bx * 128) * K;

    auto load_stage = [&](int stage, int k0) {
        __nv_bfloat16* s = smb + stage * STAGE;
        const __nv_bfloat16* srcs[4] = {srcA_h + k0, srcA_l + k0,
                                        srcB_h + k0, srcB_l + k0};
#pragma unroll
        for (int plane = 0; plane < 4; plane++) {
            if (!full && (plane & 1)) continue;   // lo planes unused in 1-pass
#pragma unroll
            for (int half = 0; half < 2; half++) {
                const int idx = tid + half * 256;
                const int row = idx >> 2, c = idx & 3;
                cp_async16(s + plane * PLANE + row * GP + c * 8,
                           srcs[plane] + (size_t)row * K + c * 8);
            }
        }
    };

    auto compute = [&](int stage) {
        const uint32_t stage_b = sb32 + stage * (STAGE * 2);
        const uint32_t aRowH = stage_b + (wm * 32 + lrowA) * 80 + lcolA;
        const uint32_t aRowL = aRowH + PLANE * 2;
        const uint32_t bRowH = stage_b + 2 * (PLANE * 2) +
                               (wn * 64 + nfselB * 8 + lrowB) * 80 + lcolB;
        const uint32_t bRowL = bRowH + PLANE * 2;
#pragma unroll
        for (int ks = 0; ks < 2; ks++) {
            const int kbyte = ks * 32;
            uint32_t ah[2][4], bh[8][2];
#pragma unroll
            for (int mf = 0; mf < 2; mf++)
                LDSM_X4(ah[mf][0], ah[mf][1], ah[mf][2], ah[mf][3],
                        aRowH + mf * 1280 + kbyte);
#pragma unroll
            for (int nfp = 0; nfp < 4; nfp++)
                LDSM_X4(bh[2 * nfp][0], bh[2 * nfp][1],
                        bh[2 * nfp + 1][0], bh[2 * nfp + 1][1],
                        bRowH + nfp * 1280 + kbyte);
#pragma unroll
            for (int mf = 0; mf < 2; mf++)
#pragma unroll
                for (int nf = 0; nf < 8; nf++)
                    MMA_BF16(acc[mf][nf], ah[mf], bh[nf]);
            if (full) {
                uint32_t al[2][4], bl[8][2];
#pragma unroll
                for (int mf = 0; mf < 2; mf++)
                    LDSM_X4(al[mf][0], al[mf][1], al[mf][2], al[mf][3],
                            aRowL + mf * 1280 + kbyte);
#pragma unroll
                for (int nfp = 0; nfp < 4; nfp++)
                    LDSM_X4(bl[2 * nfp][0], bl[2 * nfp][1],
                            bl[2 * nfp + 1][0], bl[2 * nfp + 1][1],
                            bRowL + nfp * 1280 + kbyte);
#pragma unroll
                for (int mf = 0; mf < 2; mf++)
#pragma unroll
                    for (int nf = 0; nf < 8; nf++) {
                        MMA_BF16(acc[mf][nf], al[mf], bh[nf]);
                        MMA_BF16(acc[mf][nf], ah[mf], bl[nf]);
                    }
            }
        }
    };

    load_stage(0, 0);
    cp_commit();

    const int KT = K / 32;   // 32 chunks
    int stage = 0;
    for (int kt = 0; kt < KT; kt++) {
        cp_wait<0>();
        __syncthreads();
        if (kt + 1 < KT) {
            load_stage(stage ^ 1, (kt + 1) * 32);
            cp_commit();
        }
        compute(stage);
        stage ^= 1;
    }

    if (qkv_mode && sel == 2) {
        // V epilogue: smem transpose -> V^T hi/lo bf16 planes, coalesced store
        __syncthreads();
        __nv_bfloat16* Th = smb;              // [128 cols][136]
        __nv_bfloat16* Tl = smb + 128 * 136;
#pragma unroll
        for (int mf = 0; mf < 2; mf++) {
#pragma unroll
            for (int nf = 0; nf < 8; nf++) {
                const int rl0 = wm * 32 + mf * 16 + grp, rl1 = rl0 + 8;
                const int cl0 = wn * 64 + nf * 8 + 2 * tg;
                __nv_bfloat16 h, l;
                split_bf16(acc[mf][nf][0], h, l);
                Th[cl0 * 136 + rl0] = h; Tl[cl0 * 136 + rl0] = l;
                split_bf16(acc[mf][nf][1], h, l);
                Th[(cl0 + 1) * 136 + rl0] = h; Tl[(cl0 + 1) * 136 + rl0] = l;
                split_bf16(acc[mf][nf][2], h, l);
                Th[cl0 * 136 + rl1] = h; Tl[cl0 * 136 + rl1] = l;
                split_bf16(acc[mf][nf][3], h, l);
                Th[(cl0 + 1) * 136 + rl1] = h; Tl[(cl0 + 1) * 136 + rl1] = l;
            }
        }
        __syncthreads();
#pragma unroll 4
        for (int it = 0; it < 32; it++) {
            const int idx = tid + it * 256;     // 8192 u32 per plane
            const int colL = idx >> 6;          // 0..127
            const int tp = idx & 63;            // token pair within tile
            const int token = by * 128 + tp * 2;
            const int b = token >> 11, srow = token & 2047;
            const int hglob = bx * 2 + (colL >> 6);
            const int d = colL & 63;
            const size_t off = (((size_t)b * H_ + hglob) * 64 + d) * S_ + srow;
            *(uint32_t*)&Vto[off]  = *(const uint32_t*)&Th[colL * 136 + tp * 2];
            *(uint32_t*)&Vlto[off] = *(const uint32_t*)&Tl[colL * 136 + tp * 2];
        }
        return;
    }

#pragma unroll
    for (int mf = 0; mf < 2; mf++) {
#pragma unroll
        for (int nf = 0; nf < 8; nf++) {
            const int row = by * 128 + wm * 32 + mf * 16 + grp;
            const int col = bx * 128 + wn * 64 + nf * 8 + 2 * tg;
            const size_t o00 = (size_t)row * N + col;
            const size_t o10 = (size_t)(row + 8) * N + col;
            if (qkv_mode) {
                __nv_bfloat16* O = sel ? Ko : Qo;
                *(__nv_bfloat162*)&O[o00] =
                    __floats2bfloat162_rn(acc[mf][nf][0], acc[mf][nf][1]);
                *(__nv_bfloat162*)&O[o10] =
                    __floats2bfloat162_rn(acc[mf][nf][2], acc[mf][nf][3]);
            } else {
                const float b0 = bias ? bias[col] : 0.f;
                const float b1 = bias ? bias[col + 1] : 0.f;
                Cf[o00]     = acc[mf][nf][0] + b0;
                Cf[o00 + 1] = acc[mf][nf][1] + b1;
                Cf[o10]     = acc[mf][nf][2] + b0;
                Cf[o10 + 1] = acc[mf][nf][3] + b1;
            }
        }
    }
}

// ---------------------------------------------------------------------------
// Tensor-core causal attention, P = 1 + D decomposition, all-bf16 MMAs with
// ldmatrix fragment loads (pitch 144B: conflict-free phases).
// Smem (64KB -> 3 CTAs/SM):
//   Qb @0   Kb0 @9216  Kb1 @18432  Db @27648  Vt0 @36864  Vt1 @46080
//   Vlt @55296  Lred[4][64]f32 @64512   total 65536
// ---------------------------------------------------------------------------
__global__ __launch_bounds__(256, 3) void attn_mma(
    const __nv_bfloat16* __restrict__ q, const __nv_bfloat16* __restrict__ k,
    const __nv_bfloat16* __restrict__ vt, const __nv_bfloat16* __restrict__ vlt,
    const float* __restrict__ csum,
    __nv_bfloat16* __restrict__ ch, __nv_bfloat16* __restrict__ cl) {
    extern __shared__ float sm[];
    char* smc = (char*)sm;
    const uint32_t sb32 = (uint32_t)__cvta_generic_to_shared(smc);
    const uint32_t offK[2]  = {9216u, 18432u};
    const uint32_t offVt[2] = {36864u, 46080u};
    __nv_bfloat16* Db = (__nv_bfloat16*)(smc + 27648);
    float* Lred = (float*)(smc + 64512);

    const int tid = threadIdx.x;
    const int wid = tid >> 5, lane = tid & 31;
    const int grp = lane >> 2, tg = lane & 3;
    const int wm = wid & 3;            // S^T: k-row group / DV: q-row group
    const int wn = wid >> 2;           // S^T: q-col group / DV: d-col group
    const int qt = (int)gridDim.x - 1 - (int)blockIdx.x;   // heavy first
    const int h = blockIdx.y, b = blockIdx.z;
    // ldmatrix lane-address components
    const int lrowA = lane & 15;
    const int lcolA = (lane & 16) ? 16 : 0;
    const int nfselB = (lane >> 4) & 1;
    const int lrowB = lane & 7;
    const int lcolB = (lane & 8) ? 16 : 0;

    const size_t base = ((size_t)b * S_) * D_ + (size_t)h * HD_;
    const size_t vbase = (((size_t)b * H_ + h) * 64) * S_;   // V^T row 0

    auto load_kv = [&](int stage, int kt2) {
        char* Kd = smc + offK[stage];
        char* Vd = smc + offVt[stage];
        const __nv_bfloat16* ksrc = k + base + (size_t)(kt2 * 64) * D_;
        const __nv_bfloat16* vsrc = vt + vbase + kt2 * 64;
#pragma unroll
        for (int it = 0; it < 2; it++) {
            const int idx = tid + it * 256;
            const int row = idx >> 3, c = idx & 7;
            cp_async16(Kd + row * 144 + c * 16, ksrc + (size_t)row * D_ + c * 8);
        }
#pragma unroll
        for (int it = 0; it < 2; it++) {
            const int idx = tid + it * 256;
            const int row = idx >> 3, c = idx & 7;
            cp_async16(Vd + row * 144 + c * 16, vsrc + (size_t)row * S_ + c * 8);
        }
    };
    auto load_vl = [&](int kt2) {
        const __nv_bfloat16* vsrc = vlt + vbase + kt2 * 64;
#pragma unroll
        for (int it = 0; it < 2; it++) {
            const int idx = tid + it * 256;
            const int row = idx >> 3, c = idx & 7;
            cp_async16(smc + 55296 + row * 144 + c * 16,
                       vsrc + (size_t)row * S_ + c * 8);
        }
    };

    {   // Q tile
        const __nv_bfloat16* qsrc = q + base + (size_t)(qt * 64) * D_;
#pragma unroll
        for (int it = 0; it < 2; it++) {
            const int idx = tid + it * 256;
            const int row = idx >> 3, c = idx & 7;
            cp_async16(smc + row * 144 + c * 16, qsrc + (size_t)row * D_ + c * 8);
        }
    }
    load_kv(0, 0);
    if (qt == 0) load_vl(0);
    cp_commit();

    float acc[4][4]  = {};
    float dsum[4][2] = {};
    int stage = 0;

    // Per-warp ldmatrix row bases (stage-dependent parts added in loop)
    const uint32_t aOffA = (wm * 16 + lrowA) * 144 + lcolA;            // A rows
    const uint32_t bOffQ = (wn * 32 + nfselB * 8 + lrowB) * 144 + lcolB; // B rows

    for (int kt = 0; kt <= qt; kt++) {
        cp_wait<0>();
        __syncthreads();

        if (kt < qt) {
            load_kv(stage ^ 1, kt + 1);
            if (kt + 1 == qt) load_vl(qt);
            cp_commit();
        }

        // S^T = K @ Q^T (m = k-token, n = q-token), bf16 + ldmatrix
        float s[4][4] = {};
        const uint32_t aK = sb32 + offK[stage] + aOffA;
        const uint32_t bQ = sb32 + bOffQ;
#pragma unroll
        for (int ks = 0; ks < 4; ks++) {
            const int kbyte = ks * 32;
            uint32_t a[4];
            LDSM_X4(a[0], a[1], a[2], a[3], aK + kbyte);
#pragma unroll
            for (int nfp = 0; nfp < 2; nfp++) {
                uint32_t b0[2], b1[2];
                LDSM_X4(b0[0], b0[1], b1[0], b1[1], bQ + nfp * 2304 + kbyte);
                MMA_BF16(s[2 * nfp], a, b0);
                MMA_BF16(s[2 * nfp + 1], a, b1);
            }
        }

        // d = expm1(s/4096); masked -> -1 (exact in bf16). Store D^T bf16.
        const int kg0 = kt * 64 + wm * 16 + grp;
        const int kloc = wm * 16 + grp;
#pragma unroll
        for (int nf = 0; nf < 4; nf++) {
            const int qg0  = qt * 64 + wn * 32 + nf * 8 + 2 * tg;
            const int qloc = wn * 32 + nf * 8 + 2 * tg;
            float d0, d1, d2, d3;
            {
                float x = s[nf][0] * (1.f / 4096.f);
                d0 = (kg0 <= qg0)     ? x * (1.f + x * (0.5f + x * (1.f / 6.f))) : -1.f;
                x = s[nf][1] * (1.f / 4096.f);
                d1 = (kg0 <= qg0 + 1) ? x * (1.f + x * (0.5f + x * (1.f / 6.f))) : -1.f;
                x = s[nf][2] * (1.f / 4096.f);
                d2 = (kg0 + 8 <= qg0)     ? x * (1.f + x * (0.5f + x * (1.f / 6.f))) : -1.f;
                x = s[nf][3] * (1.f / 4096.f);
                d3 = (kg0 + 8 <= qg0 + 1) ? x * (1.f + x * (0.5f + x * (1.f / 6.f))) : -1.f;
            }
            dsum[nf][0] += d0 + d2;
            dsum[nf][1] += d1 + d3;
            Db[qloc * 72 + kloc]           = __float2bfloat16_rn(d0);
            Db[(qloc + 1) * 72 + kloc]     = __float2bfloat16_rn(d1);
            Db[qloc * 72 + kloc + 8]       = __float2bfloat16_rn(d2);
            Db[(qloc + 1) * 72 + kloc + 8] = __float2bfloat16_rn(d3);
        }
        __syncthreads();

        // acc += D @ V (bf16 + ldmatrix): A = D [q][ktok], B = V^T [d][ktok]
        const uint32_t aD = sb32 + 27648 + aOffA;
        const uint32_t bV = sb32 + offVt[stage] + bOffQ;
        const uint32_t bVl = sb32 + 55296 + bOffQ;
        const bool diag = (kt == qt);
#pragma unroll
        for (int ks = 0; ks < 4; ks++) {
            const int kbyte = ks * 32;
            uint32_t a[4];
            LDSM_X4(a[0], a[1], a[2], a[3], aD + kbyte);
#pragma unroll
            for (int nfp = 0; nfp < 2; nfp++) {
                uint32_t b0[2], b1[2];
                LDSM_X4(b0[0], b0[1], b1[0], b1[1], bV + nfp * 2304 + kbyte);
                MMA_BF16(acc[2 * nfp], a, b0);
                MMA_BF16(acc[2 * nfp + 1], a, b1);
            }
            if (diag) {
#pragma unroll
                for (int nfp = 0; nfp < 2; nfp++) {
                    uint32_t b0[2], b1[2];
                    LDSM_X4(b0[0], b0[1], b1[0], b1[1], bVl + nfp * 2304 + kbyte);
                    MMA_BF16(acc[2 * nfp], a, b0);
                    MMA_BF16(acc[2 * nfp + 1], a, b1);
                }
            }
        }
        stage ^= 1;
    }

    // Reduce dsum over grp lanes
#pragma unroll
    for (int off = 16; off >= 4; off >>= 1)
#pragma unroll
        for (int nf = 0; nf < 4; nf++) {
            dsum[nf][0] += __shfl_xor_sync(0xffffffffu, dsum[nf][0], off);
            dsum[nf][1] += __shfl_xor_sync(0xffffffffu, dsum[nf][1], off);
        }
    if (grp == 0) {
#pragma unroll
        for (int nf = 0; nf < 4; nf++) {
            Lred[wm * 64 + wn * 32 + nf * 8 + 2 * tg]     = dsum[nf][0];
            Lred[wm * 64 + wn * 32 + nf * 8 + 2 * tg + 1] = dsum[nf][1];
        }
    }
    __syncthreads();

    // Epilogue: O = (acc + prefix_colsum) / l, written as bf16 hi/lo
    const float* Cs = csum + (((size_t)b * H_ + h) * 32 + qt) * 64;
    const float nk = 64.0f * (float)(qt + 1);
    const int r0 = wm * 16 + grp, r1 = r0 + 8;
    float l0 = nk, l1 = nk;
#pragma unroll
    for (int w = 0; w < 4; w++) {
        l0 += Lred[w * 64 + r0];
        l1 += Lred[w * 64 + r1];
    }
    const float inv0 = 1.0f / l0, inv1 = 1.0f / l1;
#pragma unroll
    for (int nf = 0; nf < 4; nf++) {
        const int dcol = wn * 32 + nf * 8 + 2 * tg;
        const float cs0 = Cs[dcol], cs1 = Cs[dcol + 1];
        const float o00 = (acc[nf][0] + cs0) * inv0;
        const float o01 = (acc[nf][1] + cs1) * inv0;
        const float o10 = (acc[nf][2] + cs0) * inv1;
        const float o11 = (acc[nf][3] + cs1) * inv1;
        __nv_bfloat16 h0, h1, l0b, l1b;
        const size_t a0 = base + (size_t)(qt * 64 + r0) * D_ + dcol;
        const size_t a1 = base + (size_t)(qt * 64 + r1) * D_ + dcol;
        split_bf16(o00, h0, l0b); split_bf16(o01, h1, l1b);
        *(__nv_bfloat162*)&ch[a0] = __nv_bfloat162{h0, h1};
        *(__nv_bfloat162*)&cl[a0] = __nv_bfloat162{l0b, l1b};
        split_bf16(o10, h0, l0b); split_bf16(o11, h1, l1b);
        *(__nv_bfloat162*)&ch[a1] = __nv_bfloat162{h0, h1};
        *(__nv_bfloat162*)&cl[a1] = __nv_bfloat162{l0b, l1b};
    }
}

// ---------------------------------------------------------------------------
// Launch
// ---------------------------------------------------------------------------
extern "C" void kernel_launch(void* const* d_in, const int* in_sizes, int n_in,
                              void* d_out, int out_size) {
    const float* x  = (const float*)d_in[0];
    const float* Wq = (const float*)d_in[1];
    const float* Wk = (const float*)d_in[2];
    const float* Wv = (const float*)d_in[3];
    const float* Wo = (const float*)d_in[4];
    const float* bo = (const float*)d_in[5];
    float* out = (float*)d_out;

    __nv_bfloat16 *pq, *pk, *pvt, *pvlt;
    float *pcs;
    cudaGetSymbolAddress((void**)&pq, g_q);
    cudaGetSymbolAddress((void**)&pk, g_k);
    cudaGetSymbolAddress((void**)&pvt, g_vt);
    cudaGetSymbolAddress((void**)&pvlt, g_vlt);
    cudaGetSymbolAddress((void**)&pcs, g_cs);
    __nv_bfloat16 *pxh, *pxl, *pch, *pcl, *pwh, *pwl;
    cudaGetSymbolAddress((void**)&pxh, g_xh);
    cudaGetSymbolAddress((void**)&pxl, g_xl);
    cudaGetSymbolAddress((void**)&pch, g_ch);
    cudaGetSymbolAddress((void**)&pcl, g_cl);
    cudaGetSymbolAddress((void**)&pwh, g_wh);
    cudaGetSymbolAddress((void**)&pwl, g_wl);

    const int gemm_smem = 2 * STAGE * (int)sizeof(__nv_bfloat16);  // 81920 B
    cudaFuncSetAttribute(gemm_bf16x3, cudaFuncAttributeMaxDynamicSharedMemorySize,
                         gemm_smem);
    const int attn_smem = 65536;
    cudaFuncSetAttribute(attn_mma, cudaFuncAttributeMaxDynamicSharedMemorySize,
                         attn_smem);

    // Prep
    fsplit<<<M_ * D_ / 4 / 256, 256>>>(x, pxh, pxl);
    wsplit_t<<<dim3(32, 32, 4), 256>>>(Wq, Wk, Wv, Wo, pwh, pwl);

    // Fused Q/K/V projection (V 3-pass first; Q,K 1-pass)
    dim3 gqkv(3 * D_ / 128, M_ / 128);   // (24, 64)
    gemm_bf16x3<<<gqkv, 256, gemm_smem>>>(pxh, pxl, pwh, pwl, nullptr, nullptr,
                                          pq, pk, pvt, pvlt, 1);

    // Fused prefix colsums of V
    vcolsum<<<dim3(H_, B_), 256>>>(pvt, pvlt, pcs);

    // Attention (all-bf16 MMAs + ldmatrix, 3 CTAs/SM)
    dim3 gattn(S_ / 64, H_, B_);         // (32, 16, 4)
    attn_mma<<<gattn, 256, attn_smem>>>(pq, pk, pvt, pvlt, pcs, pch, pcl);

    // Output projection (3-pass, fp32 + bias)
    dim3 gout(D_ / 128, M_ / 128);       // (8, 64)
    gemm_bf16x3<<<gout, 256, gemm_smem>>>(pch, pcl, pwh + 3 * (size_t)D_ * D_,
                                          pwl + 3 * (size_t)D_ * D_, bo, out,
                                          nullptr, nullptr, nullptr, nullptr, 0);
}

// round 17
// speedup vs baseline: 1.4251x; 1.4251x over previous
#include <cuda_runtime.h>
#include <cuda_bf16.h>
#include <cstdint>

// Problem constants
#define B_  4
#define S_  2048
#define D_  1024
#define H_  16
#define HD_ 64
#define M_  (B_ * S_)   // 8192 rows

// Scratch (allocation-free rule: __device__ globals)
__device__ __nv_bfloat16 g_q[M_ * D_];              // bf16 Q [tok][D]
__device__ __nv_bfloat16 g_k[M_ * D_];              // bf16 K [tok][D]
__device__ __nv_bfloat16 g_vt[B_ * H_ * 64 * S_];   // V^T hi [(b,h,d)][s]
__device__ __nv_bfloat16 g_vlt[B_ * H_ * 64 * S_];  // V^T lo
__device__ float g_cs[B_ * H_ * 32 * 64];           // prefix tile colsums of V
__device__ __nv_bfloat16 g_xh[M_ * D_], g_xl[M_ * D_];    // x hi/lo
__device__ __nv_bfloat16 g_ch[M_ * D_], g_cl[M_ * D_];    // ctx hi/lo
__device__ __nv_bfloat16 g_wh[4 * D_ * D_];               // W^T hi [N][K] x4
__device__ __nv_bfloat16 g_wl[4 * D_ * D_];               // W^T lo

// ---------------------------------------------------------------------------
// cp.async helpers
// ---------------------------------------------------------------------------
__device__ __forceinline__ void cp_async16(void* smem, const void* gmem) {
    uint32_t s = (uint32_t)__cvta_generic_to_shared(smem);
    asm volatile("cp.async.cg.shared.global [%0], [%1], 16;\n" :: "r"(s), "l"(gmem));
}
__device__ __forceinline__ void cp_commit() {
    asm volatile("cp.async.commit_group;\n");
}
template <int N>
__device__ __forceinline__ void cp_wait() {
    asm volatile("cp.async.wait_group %0;\n" :: "n"(N));
}

#define MMA_BF16(c, a, b)                                                     \
    asm volatile(                                                             \
        "mma.sync.aligned.m16n8k16.row.col.f32.bf16.bf16.f32 "                \
        "{%0,%1,%2,%3},{%4,%5,%6,%7},{%8,%9},{%0,%1,%2,%3};"                  \
        : "+f"(c[0]), "+f"(c[1]), "+f"(c[2]), "+f"(c[3])                      \
        : "r"(a[0]), "r"(a[1]), "r"(a[2]), "r"(a[3]), "r"(b[0]), "r"(b[1]))

__device__ __forceinline__ void split_bf16(float x, __nv_bfloat16& h, __nv_bfloat16& l) {
    h = __float2bfloat16_rn(x);
    l = __float2bfloat16_rn(x - __bfloat162float(h));
}

// ---------------------------------------------------------------------------
// Prep: elementwise fp32 -> bf16 hi/lo split (x).
// ---------------------------------------------------------------------------
__global__ __launch_bounds__(256) void fsplit(const float* __restrict__ src,
                                              __nv_bfloat16* __restrict__ h,
                                              __nv_bfloat16* __restrict__ l) {
    const int i = blockIdx.x * 256 + threadIdx.x;
    float4 v = ((const float4*)src)[i];
    __nv_bfloat16 h0, h1, h2, h3, l0, l1, l2, l3;
    split_bf16(v.x, h0, l0);
    split_bf16(v.y, h1, l1);
    split_bf16(v.z, h2, l2);
    split_bf16(v.w, h3, l3);
    __nv_bfloat162* hp = (__nv_bfloat162*)h;
    __nv_bfloat162* lp = (__nv_bfloat162*)l;
    hp[2 * i]     = __nv_bfloat162{h0, h1};
    hp[2 * i + 1] = __nv_bfloat162{h2, h3};
    lp[2 * i]     = __nv_bfloat162{l0, l1};
    lp[2 * i + 1] = __nv_bfloat162{l2, l3};
}

// ---------------------------------------------------------------------------
// Prep: W [K][N] -> W^T hi/lo bf16 [N][K], 32x32 smem tile transpose.
// ---------------------------------------------------------------------------
__global__ __launch_bounds__(256) void wsplit_t(const float* __restrict__ W0,
                                                const float* __restrict__ W1,
                                                const float* __restrict__ W2,
                                                const float* __restrict__ W3,
                                                __nv_bfloat16* __restrict__ dh,
                                                __nv_bfloat16* __restrict__ dl) {
    __shared__ float t[32][33];
    const float* W = (blockIdx.z == 0) ? W0 : (blockIdx.z == 1) ? W1
                   : (blockIdx.z == 2) ? W2 : W3;
    dh += (size_t)blockIdx.z * D_ * D_;
    dl += (size_t)blockIdx.z * D_ * D_;
    const int kx = blockIdx.x * 32, ny = blockIdx.y * 32;
    const int tx = threadIdx.x & 31, ty = threadIdx.x >> 5;
#pragma unroll
    for (int r = 0; r < 4; r++) {
        const int row = ty + r * 8;
        t[row][tx] = W[(size_t)(kx + row) * D_ + ny + tx];
    }
    __syncthreads();
#pragma unroll
    for (int r = 0; r < 4; r++) {
        const int row = ty + r * 8;
        __nv_bfloat16 h, l;
        split_bf16(t[tx][row], h, l);
        dh[(size_t)(ny + row) * D_ + kx + tx] = h;
        dl[(size_t)(ny + row) * D_ + kx + tx] = l;
    }
}

// ---------------------------------------------------------------------------
// Prep: per-tile column sums of V (V^T layout, coalesced: warp-per-d-row,
// lane-contiguous bf16x2 reads + shuffle reduce). Grid (32, H, B).
// ---------------------------------------------------------------------------
__global__ __launch_bounds__(256) void vtilesum(const __nv_bfloat16* __restrict__ vt,
                                                const __nv_bfloat16* __restrict__ vlt,
                                                float* __restrict__ cs) {
    const int t = blockIdx.x, h = blockIdx.y, b = blockIdx.z;
    const int wid = threadIdx.x >> 5, lane = threadIdx.x & 31;
#pragma unroll
    for (int dd = 0; dd < 8; dd++) {
        const int d = wid * 8 + dd;
        const size_t rbase = (((size_t)b * H_ + h) * 64 + d) * S_ + t * 64;
        const __nv_bfloat162 a = *(const __nv_bfloat162*)(vt + rbase + lane * 2);
        const __nv_bfloat162 c = *(const __nv_bfloat162*)(vlt + rbase + lane * 2);
        float s = __bfloat162float(a.x) + __bfloat162float(a.y) +
                  __bfloat162float(c.x) + __bfloat162float(c.y);
#pragma unroll
        for (int o = 16; o >= 1; o >>= 1)
            s += __shfl_xor_sync(0xffffffffu, s, o);
        if (lane == 0)
            cs[(((size_t)b * H_ + h) * 32 + t) * 64 + d] = s;
    }
}
__global__ __launch_bounds__(64) void vprefix(float* __restrict__ cs) {
    const int h = blockIdx.x, b = blockIdx.y, d = threadIdx.x;
    float s = 0.f;
    for (int t = 0; t < 32; t++) {
        const size_t off = (((size_t)b * H_ + h) * 32 + t) * 64 + d;
        s += cs[off];
        cs[off] = s;
    }
}

// ---------------------------------------------------------------------------
// bf16 tensor-core GEMM, fused over up to 3 weights, sel = blockIdx.x>>3.
// qkv_mode=1: sel 0/1 -> 1-pass bf16 (hh only; q,k need only bf16 accuracy),
//             sel 2   -> 3-pass bf16x3, epilogue smem-transposes v and emits
//                        V^T hi/lo bf16 planes [(b,h,d)][s].
// qkv_mode=0: 3-pass, fp32 + bias.
// Single-sync pipelined mainloop, 2 CTAs/SM.
// ---------------------------------------------------------------------------
#define GP 40                     // smem pitch in bf16
#define PLANE (128 * GP)          // 5120 bf16 per plane
#define STAGE (4 * PLANE)         // Ah, Al, Bh, Bl

__global__ __launch_bounds__(256, 2) void gemm_bf16x3(
    const __nv_bfloat16* __restrict__ Ah, const __nv_bfloat16* __restrict__ Al,
    const __nv_bfloat16* __restrict__ BhBase,
    const __nv_bfloat16* __restrict__ BlBase,
    const float* __restrict__ bias, float* __restrict__ Cf,
    __nv_bfloat16* __restrict__ Qo, __nv_bfloat16* __restrict__ Ko,
    __nv_bfloat16* __restrict__ Vto, __nv_bfloat16* __restrict__ Vlto,
    int qkv_mode) {
    const int K = D_, N = D_;
    extern __shared__ __nv_bfloat16 smb[];

    const int sel = blockIdx.x >> 3;
    const int bx = blockIdx.x & 7;
    const int by = blockIdx.y;
    const bool full = (qkv_mode == 0) || (sel == 2);
    const __nv_bfloat16* Bh = BhBase + (size_t)sel * D_ * D_;
    const __nv_bfloat16* Bl = BlBase + (size_t)sel * D_ * D_;

    const int tid = threadIdx.x;
    const int wid = tid >> 5, lane = tid & 31;
    const int grp = lane >> 2, tg = lane & 3;
    const int wm = wid & 3;
    const int wn = wid >> 2;

    float acc[2][8][4] = {};

    const __nv_bfloat16* srcA_h = Ah + (size_t)(by * 128) * K;
    const __nv_bfloat16* srcA_l = Al + (size_t)(by * 128) * K;
    const __nv_bfloat16* srcB_h = Bh + (size_t)(bx * 128) * K;
    const __nv_bfloat16* srcB_l = Bl + (size_t)(bx * 128) * K;

    auto load_stage = [&](int stage, int k0) {
        __nv_bfloat16* s = smb + stage * STAGE;
        const __nv_bfloat16* srcs[4] = {srcA_h + k0, srcA_l + k0,
                                        srcB_h + k0, srcB_l + k0};
#pragma unroll
        for (int plane = 0; plane < 4; plane++) {
            if (!full && (plane & 1)) continue;   // lo planes unused in 1-pass
#pragma unroll
            for (int half = 0; half < 2; half++) {
                const int idx = tid + half * 256;
                const int row = idx >> 2, c = idx & 3;
                cp_async16(s + plane * PLANE + row * GP + c * 8,
                           srcs[plane] + (size_t)row * K + c * 8);
            }
        }
    };

    auto compute = [&](int stage) {
        const uint32_t* b32 = (const uint32_t*)(smb + stage * STAGE);
        const uint32_t* pAh = b32 + (wm * 32 + grp) * 20;
        const uint32_t* pAl = pAh + PLANE / 2;
        const uint32_t* pBh = b32 + 2 * (PLANE / 2) + (wn * 64 + grp) * 20;
        const uint32_t* pBl = pBh + PLANE / 2;
#pragma unroll
        for (int ks = 0; ks < 2; ks++) {
            const int k32 = ks * 8;
            uint32_t ah[2][4], bh[8][2];
#pragma unroll
            for (int mf = 0; mf < 2; mf++) {
                const uint32_t* p = pAh + mf * 16 * 20 + k32;
                ah[mf][0] = p[tg];
                ah[mf][1] = p[160 + tg];
                ah[mf][2] = p[tg + 4];
                ah[mf][3] = p[160 + tg + 4];
            }
#pragma unroll
            for (int nf = 0; nf < 8; nf++) {
                const uint32_t* p = pBh + nf * 160 + k32;
                bh[nf][0] = p[tg];
                bh[nf][1] = p[tg + 4];
            }
#pragma unroll
            for (int mf = 0; mf < 2; mf++)
#pragma unroll
                for (int nf = 0; nf < 8; nf++)
                    MMA_BF16(acc[mf][nf], ah[mf], bh[nf]);
            if (full) {
                uint32_t al[2][4], bl[8][2];
#pragma unroll
                for (int mf = 0; mf < 2; mf++) {
                    const uint32_t* q2 = pAl + mf * 16 * 20 + k32;
                    al[mf][0] = q2[tg];
                    al[mf][1] = q2[160 + tg];
                    al[mf][2] = q2[tg + 4];
                    al[mf][3] = q2[160 + tg + 4];
                }
#pragma unroll
                for (int nf = 0; nf < 8; nf++) {
                    const uint32_t* q2 = pBl + nf * 160 + k32;
                    bl[nf][0] = q2[tg];
                    bl[nf][1] = q2[tg + 4];
                }
#pragma unroll
                for (int mf = 0; mf < 2; mf++)
#pragma unroll
                    for (int nf = 0; nf < 8; nf++) {
                        MMA_BF16(acc[mf][nf], al[mf], bh[nf]);
                        MMA_BF16(acc[mf][nf], ah[mf], bl[nf]);
                    }
            }
        }
    };

    load_stage(0, 0);
    cp_commit();

    const int KT = K / 32;   // 32 chunks
    int stage = 0;
    for (int kt = 0; kt < KT; kt++) {
        cp_wait<0>();
        __syncthreads();
        if (kt + 1 < KT) {
            load_stage(stage ^ 1, (kt + 1) * 32);
            cp_commit();
        }
        compute(stage);
        stage ^= 1;
    }

    if (qkv_mode && sel == 2) {
        // V epilogue: smem transpose -> V^T hi/lo bf16 planes, coalesced store
        __syncthreads();                      // mainloop smem reads done
        __nv_bfloat16* Th = smb;              // [128 cols][136]
        __nv_bfloat16* Tl = smb + 128 * 136;
#pragma unroll
        for (int mf = 0; mf < 2; mf++) {
#pragma unroll
            for (int nf = 0; nf < 8; nf++) {
                const int rl0 = wm * 32 + mf * 16 + grp, rl1 = rl0 + 8;
                const int cl0 = wn * 64 + nf * 8 + 2 * tg;
                __nv_bfloat16 h, l;
                split_bf16(acc[mf][nf][0], h, l);
                Th[cl0 * 136 + rl0] = h; Tl[cl0 * 136 + rl0] = l;
                split_bf16(acc[mf][nf][1], h, l);
                Th[(cl0 + 1) * 136 + rl0] = h; Tl[(cl0 + 1) * 136 + rl0] = l;
                split_bf16(acc[mf][nf][2], h, l);
                Th[cl0 * 136 + rl1] = h; Tl[cl0 * 136 + rl1] = l;
                split_bf16(acc[mf][nf][3], h, l);
                Th[(cl0 + 1) * 136 + rl1] = h; Tl[(cl0 + 1) * 136 + rl1] = l;
            }
        }
        __syncthreads();
#pragma unroll 4
        for (int it = 0; it < 32; it++) {
            const int idx = tid + it * 256;     // 8192 u32 per plane
            const int colL = idx >> 6;          // 0..127
            const int tp = idx & 63;            // token pair within tile
            const int token = by * 128 + tp * 2;
            const int b = token >> 11, srow = token & 2047;
            const int hglob = bx * 2 + (colL >> 6);
            const int d = colL & 63;
            const size_t off = (((size_t)b * H_ + hglob) * 64 + d) * S_ + srow;
            *(uint32_t*)&Vto[off]  = *(const uint32_t*)&Th[colL * 136 + tp * 2];
            *(uint32_t*)&Vlto[off] = *(const uint32_t*)&Tl[colL * 136 + tp * 2];
        }
        return;
    }

#pragma unroll
    for (int mf = 0; mf < 2; mf++) {
#pragma unroll
        for (int nf = 0; nf < 8; nf++) {
            const int row = by * 128 + wm * 32 + mf * 16 + grp;
            const int col = bx * 128 + wn * 64 + nf * 8 + 2 * tg;
            const size_t o00 = (size_t)row * N + col;
            const size_t o10 = (size_t)(row + 8) * N + col;
            if (qkv_mode) {
                __nv_bfloat16* O = sel ? Ko : Qo;
                *(__nv_bfloat162*)&O[o00] =
                    __floats2bfloat162_rn(acc[mf][nf][0], acc[mf][nf][1]);
                *(__nv_bfloat162*)&O[o10] =
                    __floats2bfloat162_rn(acc[mf][nf][2], acc[mf][nf][3]);
            } else {
                const float b0 = bias ? bias[col] : 0.f;
                const float b1 = bias ? bias[col + 1] : 0.f;
                Cf[o00]     = acc[mf][nf][0] + b0;
                Cf[o00 + 1] = acc[mf][nf][1] + b1;
                Cf[o10]     = acc[mf][nf][2] + b0;
                Cf[o10 + 1] = acc[mf][nf][3] + b1;
            }
        }
    }
}

// ---------------------------------------------------------------------------
// Tensor-core causal attention, P = 1 + D decomposition, all-bf16 MMAs.
// QK^T: q,k bf16 [tok][d]. DV: D bf16 [q][ktok] (A), V^T bf16 [d][ktok] (B);
// diagonal tile adds a (D, V^T_lo) pass so the -1 masked cancellation against
// the precomputed colsum prefix is exact. K/V^T double-buffered with prefetch.
// Smem (64KB -> 3 CTAs/SM):
//   Qb  [64][72]bf16 @0      Kb0 @9216   Kb1 @18432
//   Db  [64][72]bf16 @27648  Vt0 @36864  Vt1 @46080
//   Vlt @55296               Lred[4][64]f32 @64512   total 65536
// ---------------------------------------------------------------------------
#define KPB36 36   // bf16 tile pitch in u32 (72 bf16 = 144B)

__global__ __launch_bounds__(256, 3) void attn_mma(
    const __nv_bfloat16* __restrict__ q, const __nv_bfloat16* __restrict__ k,
    const __nv_bfloat16* __restrict__ vt, const __nv_bfloat16* __restrict__ vlt,
    const float* __restrict__ csum,
    __nv_bfloat16* __restrict__ ch, __nv_bfloat16* __restrict__ cl) {
    extern __shared__ float sm[];
    char* smc = (char*)sm;
    const uint32_t offK[2]  = {9216u, 18432u};
    const uint32_t offVt[2] = {36864u, 46080u};
    __nv_bfloat16* Db = (__nv_bfloat16*)(smc + 27648);
    char* Vlt = smc + 55296;
    float* Lred = (float*)(smc + 64512);

    const int tid = threadIdx.x;
    const int wid = tid >> 5, lane = tid & 31;
    const int grp = lane >> 2, tg = lane & 3;
    const int wm = wid & 3;            // S^T: k-row group / DV: q-row group
    const int wn = wid >> 2;           // S^T: q-col group / DV: d-col group
    const int qt = (int)gridDim.x - 1 - (int)blockIdx.x;   // heavy first
    const int h = blockIdx.y, b = blockIdx.z;

    const size_t base = ((size_t)b * S_) * D_ + (size_t)h * HD_;
    const size_t vbase = (((size_t)b * H_ + h) * 64) * S_;   // V^T row 0

    auto load_kv = [&](int stage, int kt2) {
        char* Kd = smc + offK[stage];
        char* Vd = smc + offVt[stage];
        const __nv_bfloat16* ksrc = k + base + (size_t)(kt2 * 64) * D_;
        const __nv_bfloat16* vsrc = vt + vbase + kt2 * 64;
#pragma unroll
        for (int it = 0; it < 2; it++) {          // K: 512 x 16B
            const int idx = tid + it * 256;
            const int row = idx >> 3, c = idx & 7;
            cp_async16(Kd + row * 144 + c * 16, ksrc + (size_t)row * D_ + c * 8);
        }
#pragma unroll
        for (int it = 0; it < 2; it++) {          // V^T: 512 x 16B
            const int idx = tid + it * 256;
            const int row = idx >> 3, c = idx & 7;
            cp_async16(Vd + row * 144 + c * 16, vsrc + (size_t)row * S_ + c * 8);
        }
    };
    auto load_vl = [&](int kt2) {
        const __nv_bfloat16* vsrc = vlt + vbase + kt2 * 64;
#pragma unroll
        for (int it = 0; it < 2; it++) {
            const int idx = tid + it * 256;
            const int row = idx >> 3, c = idx & 7;
            cp_async16(Vlt + row * 144 + c * 16, vsrc + (size_t)row * S_ + c * 8);
        }
    };

    {   // Q tile
        const __nv_bfloat16* qsrc = q + base + (size_t)(qt * 64) * D_;
#pragma unroll
        for (int it = 0; it < 2; it++) {
            const int idx = tid + it * 256;
            const int row = idx >> 3, c = idx & 7;
            cp_async16(smc + row * 144 + c * 16, qsrc + (size_t)row * D_ + c * 8);
        }
    }
    load_kv(0, 0);
    if (qt == 0) load_vl(0);
    cp_commit();

    float acc[4][4]  = {};
    float dsum[4][2] = {};
    int stage = 0;

    for (int kt = 0; kt <= qt; kt++) {
        cp_wait<0>();
        __syncthreads();

        if (kt < qt) {
            load_kv(stage ^ 1, kt + 1);
            if (kt + 1 == qt) load_vl(qt);
            cp_commit();
        }

        // S^T = K @ Q^T (m = k-token, n = q-token), bf16
        float s[4][4] = {};
        const uint32_t* Ka = (const uint32_t*)(smc + offK[stage]) +
                             (wm * 16 + grp) * KPB36;
        const uint32_t* Qbase32 = (const uint32_t*)smc;
#pragma unroll
        for (int ks = 0; ks < 4; ks++) {
            const int k32 = ks * 8;
            uint32_t a[4];
            a[0] = Ka[k32 + tg];
            a[1] = Ka[8 * KPB36 + k32 + tg];
            a[2] = Ka[k32 + tg + 4];
            a[3] = Ka[8 * KPB36 + k32 + tg + 4];
#pragma unroll
            for (int nf = 0; nf < 4; nf++) {
                const uint32_t* Qp = Qbase32 +
                    (wn * 32 + nf * 8 + grp) * KPB36 + k32 + tg;
                uint32_t bb[2] = { Qp[0], Qp[4] };
                MMA_BF16(s[nf], a, bb);
            }
        }

        // d = expm1(s/4096); masked -> -1 (exact in bf16). Store D^T bf16.
        const int kg0 = kt * 64 + wm * 16 + grp;
        const int kloc = wm * 16 + grp;
#pragma unroll
        for (int nf = 0; nf < 4; nf++) {
            const int qg0  = qt * 64 + wn * 32 + nf * 8 + 2 * tg;
            const int qloc = wn * 32 + nf * 8 + 2 * tg;
            float d0, d1, d2, d3;
            {
                float x = s[nf][0] * (1.f / 4096.f);
                d0 = (kg0 <= qg0)     ? x * (1.f + x * (0.5f + x * (1.f / 6.f))) : -1.f;
                x = s[nf][1] * (1.f / 4096.f);
                d1 = (kg0 <= qg0 + 1) ? x * (1.f + x * (0.5f + x * (1.f / 6.f))) : -1.f;
                x = s[nf][2] * (1.f / 4096.f);
                d2 = (kg0 + 8 <= qg0)     ? x * (1.f + x * (0.5f + x * (1.f / 6.f))) : -1.f;
                x = s[nf][3] * (1.f / 4096.f);
                d3 = (kg0 + 8 <= qg0 + 1) ? x * (1.f + x * (0.5f + x * (1.f / 6.f))) : -1.f;
            }
            dsum[nf][0] += d0 + d2;
            dsum[nf][1] += d1 + d3;
            Db[qloc * 72 + kloc]           = __float2bfloat16_rn(d0);
            Db[(qloc + 1) * 72 + kloc]     = __float2bfloat16_rn(d1);
            Db[qloc * 72 + kloc + 8]       = __float2bfloat16_rn(d2);
            Db[(qloc + 1) * 72 + kloc + 8] = __float2bfloat16_rn(d3);
        }
        __syncthreads();

        // acc += D @ V (bf16): A = D [q][ktok], B = V^T [d][ktok]
        const uint32_t* Da = (const uint32_t*)Db + (wm * 16 + grp) * KPB36;
        const uint32_t* Vb32 = (const uint32_t*)(smc + offVt[stage]);
        const bool diag = (kt == qt);
#pragma unroll
        for (int ks = 0; ks < 4; ks++) {
            const int k32 = ks * 8;
            uint32_t a[4];
            a[0] = Da[k32 + tg];
            a[1] = Da[8 * KPB36 + k32 + tg];
            a[2] = Da[k32 + tg + 4];
            a[3] = Da[8 * KPB36 + k32 + tg + 4];
#pragma unroll
            for (int nf = 0; nf < 4; nf++) {
                const uint32_t* Vp = Vb32 +
                    (wn * 32 + nf * 8 + grp) * KPB36 + k32 + tg;
                uint32_t bb[2] = { Vp[0], Vp[4] };
                MMA_BF16(acc[nf], a, bb);
            }
            if (diag) {
                const uint32_t* Vl32 = (const uint32_t*)Vlt;
#pragma unroll
                for (int nf = 0; nf < 4; nf++) {
                    const uint32_t* Vp = Vl32 +
                        (wn * 32 + nf * 8 + grp) * KPB36 + k32 + tg;
                    uint32_t bb[2] = { Vp[0], Vp[4] };
                    MMA_BF16(acc[nf], a, bb);
                }
            }
        }
        stage ^= 1;
    }

    // Reduce dsum over grp lanes
#pragma unroll
    for (int off = 16; off >= 4; off >>= 1)
#pragma unroll
        for (int nf = 0; nf < 4; nf++) {
            dsum[nf][0] += __shfl_xor_sync(0xffffffffu, dsum[nf][0], off);
            dsum[nf][1] += __shfl_xor_sync(0xffffffffu, dsum[nf][1], off);
        }
    if (grp == 0) {
#pragma unroll
        for (int nf = 0; nf < 4; nf++) {
            Lred[wm * 64 + wn * 32 + nf * 8 + 2 * tg]     = dsum[nf][0];
            Lred[wm * 64 + wn * 32 + nf * 8 + 2 * tg + 1] = dsum[nf][1];
        }
    }
    __syncthreads();

    // Epilogue: O = (acc + prefix_colsum) / l, written as bf16 hi/lo
    const float* Cs = csum + (((size_t)b * H_ + h) * 32 + qt) * 64;
    const float nk = 64.0f * (float)(qt + 1);
    const int r0 = wm * 16 + grp, r1 = r0 + 8;
    float l0 = nk, l1 = nk;
#pragma unroll
    for (int w = 0; w < 4; w++) {
        l0 += Lred[w * 64 + r0];
        l1 += Lred[w * 64 + r1];
    }
    const float inv0 = 1.0f / l0, inv1 = 1.0f / l1;
#pragma unroll
    for (int nf = 0; nf < 4; nf++) {
        const int dcol = wn * 32 + nf * 8 + 2 * tg;
        const float cs0 = Cs[dcol], cs1 = Cs[dcol + 1];
        const float o00 = (acc[nf][0] + cs0) * inv0;
        const float o01 = (acc[nf][1] + cs1) * inv0;
        const float o10 = (acc[nf][2] + cs0) * inv1;
        const float o11 = (acc[nf][3] + cs1) * inv1;
        __nv_bfloat16 h0, h1, l0b, l1b;
        const size_t a0 = base + (size_t)(qt * 64 + r0) * D_ + dcol;
        const size_t a1 = base + (size_t)(qt * 64 + r1) * D_ + dcol;
        split_bf16(o00, h0, l0b); split_bf16(o01, h1, l1b);
        *(__nv_bfloat162*)&ch[a0] = __nv_bfloat162{h0, h1};
        *(__nv_bfloat162*)&cl[a0] = __nv_bfloat162{l0b, l1b};
        split_bf16(o10, h0, l0b); split_bf16(o11, h1, l1b);
        *(__nv_bfloat162*)&ch[a1] = __nv_bfloat162{h0, h1};
        *(__nv_bfloat162*)&cl[a1] = __nv_bfloat162{l0b, l1b};
    }
}

// ---------------------------------------------------------------------------
// Launch
// ---------------------------------------------------------------------------
extern "C" void kernel_launch(void* const* d_in, const int* in_sizes, int n_in,
                              void* d_out, int out_size) {
    const float* x  = (const float*)d_in[0];
    const float* Wq = (const float*)d_in[1];
    const float* Wk = (const float*)d_in[2];
    const float* Wv = (const float*)d_in[3];
    const float* Wo = (const float*)d_in[4];
    const float* bo = (const float*)d_in[5];
    float* out = (float*)d_out;

    __nv_bfloat16 *pq, *pk, *pvt, *pvlt;
    float *pcs;
    cudaGetSymbolAddress((void**)&pq, g_q);
    cudaGetSymbolAddress((void**)&pk, g_k);
    cudaGetSymbolAddress((void**)&pvt, g_vt);
    cudaGetSymbolAddress((void**)&pvlt, g_vlt);
    cudaGetSymbolAddress((void**)&pcs, g_cs);
    __nv_bfloat16 *pxh, *pxl, *pch, *pcl, *pwh, *pwl;
    cudaGetSymbolAddress((void**)&pxh, g_xh);
    cudaGetSymbolAddress((void**)&pxl, g_xl);
    cudaGetSymbolAddress((void**)&pch, g_ch);
    cudaGetSymbolAddress((void**)&pcl, g_cl);
    cudaGetSymbolAddress((void**)&pwh, g_wh);
    cudaGetSymbolAddress((void**)&pwl, g_wl);

    const int gemm_smem = 2 * STAGE * (int)sizeof(__nv_bfloat16);  // 81920 B
    cudaFuncSetAttribute(gemm_bf16x3, cudaFuncAttributeMaxDynamicSharedMemorySize,
                         gemm_smem);
    const int attn_smem = 65536;
    cudaFuncSetAttribute(attn_mma, cudaFuncAttributeMaxDynamicSharedMemorySize,
                         attn_smem);

    // Prep
    fsplit<<<M_ * D_ / 4 / 256, 256>>>(x, pxh, pxl);
    wsplit_t<<<dim3(32, 32, 4), 256>>>(Wq, Wk, Wv, Wo, pwh, pwl);

    // Fused Q/K/V projection (Q,K 1-pass; V 3-pass with V^T hi/lo epilogue)
    dim3 gqkv(3 * D_ / 128, M_ / 128);   // (24, 64)
    gemm_bf16x3<<<gqkv, 256, gemm_smem>>>(pxh, pxl, pwh, pwl, nullptr, nullptr,
                                          pq, pk, pvt, pvlt, 1);

    // Prefix tile colsums of V (coalesced, 2048 CTAs)
    vtilesum<<<dim3(32, H_, B_), 256>>>(pvt, pvlt, pcs);
    vprefix<<<dim3(H_, B_), 64>>>(pcs);

    // Attention (all-bf16 MMAs, 3 CTAs/SM); epilogue emits ctx bf16 hi/lo
    dim3 gattn(S_ / 64, H_, B_);         // (32, 16, 4)
    attn_mma<<<gattn, 256, attn_smem>>>(pq, pk, pvt, pvlt, pcs, pch, pcl);

    // Output projection (3-pass, fp32 + bias)
    dim3 gout(D_ / 128, M_ / 128);       // (8, 64)
    gemm_bf16x3<<<gout, 256, gemm_smem>>>(pch, pcl, pwh + 3 * (size_t)D_ * D_,
                                          pwl + 3 * (size_t)D_ * D_, bo, out,
                                          nullptr, nullptr, nullptr, nullptr, 0);
}